// round 1
// baseline (speedup 1.0000x reference)
#include <cuda_runtime.h>

#define MROWS 8192
#define NCOLS 8192
#define DIN   128
#define DH    256
#define TOPK  512

#define BM 128
#define BN 128
#define BK 16
#define NTHREADS 256

#define NBLK_X (NCOLS / BN)   // 64
#define NBLK_Y (MROWS / BM)   // 64
#define NBLOCKS (NBLK_X * NBLK_Y)  // 4096

#define CAND_BUF  32768
#define CAND_SORT 4096

// ---------------- scratch (device globals; no allocation allowed) ----------
__device__ float g_hid0[MROWS * DH];
__device__ float g_hid1[NCOLS * DH];
__device__ float g_md0[MROWS * DH];
__device__ float g_md1[NCOLS * DH];
__device__ float g_blockmax[NBLOCKS];
__device__ float g_thresh;
__device__ unsigned int g_ccount;
__device__ unsigned long long g_cand[CAND_BUF];

// monotone float -> uint key
__device__ __forceinline__ unsigned int fkey(float f) {
    unsigned int u = __float_as_uint(f);
    return (u & 0x80000000u) ? ~u : (u | 0x80000000u);
}

// ---------------- MLP GEMM: O = act(A @ W + b), N = DH = 256 ---------------
// layer 0: A = desc (param), K = DIN, relu, O = g_hid*
// layer 1: A = g_hid*,       K = DH,  linear, O = g_md*
__global__ __launch_bounds__(NTHREADS, 2)
void mlp_gemm_kernel(const float* __restrict__ in0, const float* __restrict__ in1,
                     const float* __restrict__ Wd0, const float* __restrict__ Wd1,
                     const float* __restrict__ bd0, const float* __restrict__ bd1,
                     int layer)
{
    const int z = blockIdx.z;
    const float* A;
    float* O;
    int K, relu;
    if (layer == 0) {
        A = z ? in1 : in0;
        O = z ? g_hid1 : g_hid0;
        K = DIN; relu = 1;
    } else {
        A = z ? g_hid1 : g_hid0;
        O = z ? g_md1 : g_md0;
        K = DH; relu = 0;
    }
    const float* W = z ? Wd1 : Wd0;
    const float* bias = z ? bd1 : bd0;

    __shared__ float As[BK][BM];
    __shared__ float Bs[BK][BN];

    const int tid = threadIdx.x;
    const int tx = tid & 15, ty = tid >> 4;
    const int r0 = blockIdx.y * BM;
    const int c0 = blockIdx.x * BN;

    float acc[8][8];
#pragma unroll
    for (int i = 0; i < 8; i++)
#pragma unroll
        for (int j = 0; j < 8; j++) acc[i][j] = 0.0f;

    for (int k0 = 0; k0 < K; k0 += BK) {
        // A tile (row-major, K-contiguous) -> As[k][m]
#pragma unroll
        for (int i = 0; i < 2; i++) {
            int f = tid * 2 + i;
            int row = f >> 2;
            int kq = (f & 3) << 2;
            float4 v = *(const float4*)(A + (size_t)(r0 + row) * K + k0 + kq);
            As[kq + 0][row] = v.x; As[kq + 1][row] = v.y;
            As[kq + 2][row] = v.z; As[kq + 3][row] = v.w;
        }
        // W tile (row-major [K, DH]) -> Bs[k][n]
#pragma unroll
        for (int i = 0; i < 2; i++) {
            int f = tid * 2 + i;
            int kk = f >> 5;
            int nq = (f & 31) << 2;
            *(float4*)&Bs[kk][nq] =
                *(const float4*)(W + (size_t)(k0 + kk) * DH + c0 + nq);
        }
        __syncthreads();
#pragma unroll
        for (int kk = 0; kk < BK; kk++) {
            float a[8], b[8];
            *(float4*)&a[0] = *(float4*)&As[kk][ty * 8];
            *(float4*)&a[4] = *(float4*)&As[kk][ty * 8 + 4];
            *(float4*)&b[0] = *(float4*)&Bs[kk][tx * 8];
            *(float4*)&b[4] = *(float4*)&Bs[kk][tx * 8 + 4];
#pragma unroll
            for (int i = 0; i < 8; i++)
#pragma unroll
                for (int j = 0; j < 8; j++)
                    acc[i][j] = fmaf(a[i], b[j], acc[i][j]);
        }
        __syncthreads();
    }

    float bv[8];
    *(float4*)&bv[0] = *(const float4*)(bias + c0 + tx * 8);
    *(float4*)&bv[4] = *(const float4*)(bias + c0 + tx * 8 + 4);

#pragma unroll
    for (int i = 0; i < 8; i++) {
        int row = r0 + ty * 8 + i;
        float4 v0, v1;
        v0.x = acc[i][0] + bv[0]; v0.y = acc[i][1] + bv[1];
        v0.z = acc[i][2] + bv[2]; v0.w = acc[i][3] + bv[3];
        v1.x = acc[i][4] + bv[4]; v1.y = acc[i][5] + bv[5];
        v1.z = acc[i][6] + bv[6]; v1.w = acc[i][7] + bv[7];
        if (relu) {
            v0.x = fmaxf(v0.x, 0.f); v0.y = fmaxf(v0.y, 0.f);
            v0.z = fmaxf(v0.z, 0.f); v0.w = fmaxf(v0.w, 0.f);
            v1.x = fmaxf(v1.x, 0.f); v1.y = fmaxf(v1.y, 0.f);
            v1.z = fmaxf(v1.z, 0.f); v1.w = fmaxf(v1.w, 0.f);
        }
        *(float4*)(O + (size_t)row * DH + c0 + tx * 8) = v0;
        *(float4*)(O + (size_t)row * DH + c0 + tx * 8 + 4) = v1;
    }
}

// ---------------- sim GEMM: C = md0 @ md1^T, with per-block max ------------
__global__ __launch_bounds__(NTHREADS, 2)
void sim_gemm_kernel(float* __restrict__ C)
{
    const float* __restrict__ A = g_md0;   // [MROWS, DH]
    const float* __restrict__ B = g_md1;   // [NCOLS, DH]

    __shared__ float As[BK][BM];
    __shared__ float Bs[BK][BN];
    __shared__ float smax[8];

    const int tid = threadIdx.x;
    const int tx = tid & 15, ty = tid >> 4;
    const int r0 = blockIdx.y * BM;
    const int c0 = blockIdx.x * BN;

    float acc[8][8];
#pragma unroll
    for (int i = 0; i < 8; i++)
#pragma unroll
        for (int j = 0; j < 8; j++) acc[i][j] = 0.0f;

    for (int k0 = 0; k0 < DH; k0 += BK) {
#pragma unroll
        for (int i = 0; i < 2; i++) {
            int f = tid * 2 + i;
            int row = f >> 2;
            int kq = (f & 3) << 2;
            float4 va = *(const float4*)(A + (size_t)(r0 + row) * DH + k0 + kq);
            As[kq + 0][row] = va.x; As[kq + 1][row] = va.y;
            As[kq + 2][row] = va.z; As[kq + 3][row] = va.w;
            float4 vb = *(const float4*)(B + (size_t)(c0 + row) * DH + k0 + kq);
            Bs[kq + 0][row] = vb.x; Bs[kq + 1][row] = vb.y;
            Bs[kq + 2][row] = vb.z; Bs[kq + 3][row] = vb.w;
        }
        __syncthreads();
#pragma unroll
        for (int kk = 0; kk < BK; kk++) {
            float a[8], b[8];
            *(float4*)&a[0] = *(float4*)&As[kk][ty * 8];
            *(float4*)&a[4] = *(float4*)&As[kk][ty * 8 + 4];
            *(float4*)&b[0] = *(float4*)&Bs[kk][tx * 8];
            *(float4*)&b[4] = *(float4*)&Bs[kk][tx * 8 + 4];
#pragma unroll
            for (int i = 0; i < 8; i++)
#pragma unroll
                for (int j = 0; j < 8; j++)
                    acc[i][j] = fmaf(a[i], b[j], acc[i][j]);
        }
        __syncthreads();
    }

    float m = -3.0e38f;
#pragma unroll
    for (int i = 0; i < 8; i++) {
        int row = r0 + ty * 8 + i;
        float4 v0, v1;
        v0.x = acc[i][0]; v0.y = acc[i][1]; v0.z = acc[i][2]; v0.w = acc[i][3];
        v1.x = acc[i][4]; v1.y = acc[i][5]; v1.z = acc[i][6]; v1.w = acc[i][7];
        *(float4*)(C + (size_t)row * NCOLS + c0 + tx * 8) = v0;
        *(float4*)(C + (size_t)row * NCOLS + c0 + tx * 8 + 4) = v1;
#pragma unroll
        for (int j = 0; j < 8; j++) m = fmaxf(m, acc[i][j]);
    }
#pragma unroll
    for (int o = 16; o; o >>= 1) m = fmaxf(m, __shfl_xor_sync(0xffffffffu, m, o));
    if ((tid & 31) == 0) smax[tid >> 5] = m;
    __syncthreads();
    if (tid == 0) {
        float mm = smax[0];
#pragma unroll
        for (int i = 1; i < 8; i++) mm = fmaxf(mm, smax[i]);
        g_blockmax[blockIdx.y * gridDim.x + blockIdx.x] = mm;
    }
}

// ---------------- threshold: 512th-largest block max (valid lower bound) ---
__global__ void thresh_kernel()
{
    __shared__ float s[NBLOCKS];
    const int tid = threadIdx.x;  // 1024 threads
    for (int i = tid; i < NBLOCKS; i += 1024) s[i] = g_blockmax[i];
    __syncthreads();
    // bitonic sort, descending
    for (int k = 2; k <= NBLOCKS; k <<= 1) {
        for (int j = k >> 1; j > 0; j >>= 1) {
            for (int i = tid; i < NBLOCKS; i += 1024) {
                int ixj = i ^ j;
                if (ixj > i) {
                    bool desc = ((i & k) == 0);
                    float a = s[i], b = s[ixj];
                    if (desc ? (a < b) : (a > b)) { s[i] = b; s[ixj] = a; }
                }
            }
            __syncthreads();
        }
    }
    if (tid == 0) {
        g_thresh = s[TOPK - 1];
        g_ccount = 0;
    }
}

// ---------------- collect candidates >= threshold ---------------------------
__device__ __forceinline__ void push_cand(float v, unsigned int idx)
{
    unsigned int pos = atomicAdd(&g_ccount, 1u);
    if (pos < CAND_BUF) {
        unsigned long long e =
            ((unsigned long long)fkey(v) << 32) | (unsigned int)(~idx);
        g_cand[pos] = e;
    }
}

__global__ void collect_kernel(const float* __restrict__ S)
{
    const float T = g_thresh;
    const size_t total4 = (size_t)MROWS * NCOLS / 4;
    const size_t stride = (size_t)gridDim.x * blockDim.x;
    for (size_t q = (size_t)blockIdx.x * blockDim.x + threadIdx.x;
         q < total4; q += stride) {
        float4 v = ((const float4*)S)[q];
        unsigned int base = (unsigned int)(q * 4);
        if (v.x >= T) push_cand(v.x, base + 0);
        if (v.y >= T) push_cand(v.y, base + 1);
        if (v.z >= T) push_cand(v.z, base + 2);
        if (v.w >= T) push_cand(v.w, base + 3);
    }
}

// ---------------- final: sort candidates, emit (row, col) pairs ------------
__global__ void final_kernel(float* __restrict__ out)
{
    __shared__ unsigned long long s[CAND_SORT];
    __shared__ unsigned long long red[32];
    const int tid = threadIdx.x;  // 1024 threads
    unsigned int cnt = g_ccount;
    if (cnt > CAND_BUF) cnt = CAND_BUF;

    if (cnt <= CAND_SORT) {
        for (int i = tid; i < CAND_SORT; i += 1024)
            s[i] = (i < (int)cnt) ? g_cand[i] : 0ull;
        __syncthreads();
        for (int k = 2; k <= CAND_SORT; k <<= 1) {
            for (int j = k >> 1; j > 0; j >>= 1) {
                for (int i = tid; i < CAND_SORT; i += 1024) {
                    int ixj = i ^ j;
                    if (ixj > i) {
                        bool desc = ((i & k) == 0);
                        unsigned long long a = s[i], b = s[ixj];
                        if (desc ? (a < b) : (a > b)) { s[i] = b; s[ixj] = a; }
                    }
                }
                __syncthreads();
            }
        }
        for (int i = tid; i < TOPK; i += 1024) {
            unsigned int idx = ~(unsigned int)(s[i] & 0xFFFFFFFFull);
            out[2 * i + 0] = (float)(idx >> 13);
            out[2 * i + 1] = (float)(idx & (NCOLS - 1));
        }
    } else {
        // rare fallback: iterative max-selection over global candidates
        for (int r = 0; r < TOPK; r++) {
            unsigned long long best = 0ull;
            for (unsigned int i = tid; i < cnt; i += 1024) {
                unsigned long long v = g_cand[i];
                if (v > best) best = v;
            }
#pragma unroll
            for (int o = 16; o; o >>= 1) {
                unsigned long long other = __shfl_down_sync(0xffffffffu, best, o);
                if (other > best) best = other;
            }
            if ((tid & 31) == 0) red[tid >> 5] = best;
            __syncthreads();
            if (tid < 32) {
                unsigned long long b = red[tid];
#pragma unroll
                for (int o = 16; o; o >>= 1) {
                    unsigned long long other = __shfl_down_sync(0xffffffffu, b, o);
                    if (other > b) b = other;
                }
                if (tid == 0) red[0] = b;
            }
            __syncthreads();
            best = red[0];
            for (unsigned int i = tid; i < cnt; i += 1024)
                if (g_cand[i] == best) g_cand[i] = 0ull;
            if (tid == 0) {
                unsigned int idx = ~(unsigned int)(best & 0xFFFFFFFFull);
                out[2 * r + 0] = (float)(idx >> 13);
                out[2 * r + 1] = (float)(idx & (NCOLS - 1));
            }
            __syncthreads();
        }
    }
}

// ---------------- launch ----------------------------------------------------
extern "C" void kernel_launch(void* const* d_in, const int* in_sizes, int n_in,
                              void* d_out, int out_size)
{
    const float* desc0 = (const float*)d_in[0];
    const float* desc1 = (const float*)d_in[1];
    const float* W0a = (const float*)d_in[2];
    const float* b0a = (const float*)d_in[3];
    const float* W0b = (const float*)d_in[4];
    const float* b0b = (const float*)d_in[5];
    const float* W1a = (const float*)d_in[6];
    const float* b1a = (const float*)d_in[7];
    const float* W1b = (const float*)d_in[8];
    const float* b1b = (const float*)d_in[9];

    float* out = (float*)d_out;
    float* sim = out + 2 * TOPK;  // indices first, then sim [8192, 8192]

    dim3 mgrid(DH / BN, MROWS / BM, 2);   // (2, 64, 2)
    mlp_gemm_kernel<<<mgrid, NTHREADS>>>(desc0, desc1, W0a, W1a, b0a, b1a, 0);
    mlp_gemm_kernel<<<mgrid, NTHREADS>>>(desc0, desc1, W0b, W1b, b0b, b1b, 1);

    dim3 sgrid(NBLK_X, NBLK_Y);           // (64, 64)
    sim_gemm_kernel<<<sgrid, NTHREADS>>>(sim);

    thresh_kernel<<<1, 1024>>>();
    collect_kernel<<<2048, 256>>>(sim);
    final_kernel<<<1, 1024>>>(out);
}

// round 5
// speedup vs baseline: 1.0077x; 1.0077x over previous
#include <cuda_runtime.h>
#include <cstdint>

#define MROWS 8192
#define NCOLS 8192
#define DIN   128
#define DH    256
#define TOPK  512

// ---------- MLP tiling ----------
#define BM 128
#define BN 128
#define BK 16
#define NTHREADS 256

// ---------- sim tiling (mma.sync tf32) ----------
#define KTOT 512            // stored per row: [hi 256 | lo(exact residual) 256]
#define SBK  16             // k per pipeline stage
#define NSTAGE 48           // 3 terms x 16 stages (K_eff = 768)
#define SROWSTRIDE 20       // 16 floats + 4 pad (bank-conflict-free)

#define NBX (NCOLS / 128)   // 64
#define NBY (MROWS / 128)   // 64
#define NBLOCKS (NBX * NBY) // 4096

#define CAND_BUF  32768
#define CAND_SORT 4096

// ---------------- scratch (device globals; no allocation allowed) ----------
__device__ __align__(128) float g_hid0[MROWS * DH];
__device__ __align__(128) float g_hid1[NCOLS * DH];
__device__ __align__(128) float g_a2[MROWS * KTOT];   // [row][0:256)=tf32 hi, [256:512)=fp32 residual
__device__ __align__(128) float g_b2[NCOLS * KTOT];
__device__ float g_blockmax[NBLOCKS];
__device__ float g_thresh;
__device__ unsigned int g_ccount;
__device__ unsigned long long g_cand[CAND_BUF];

// monotone float -> uint key
__device__ __forceinline__ unsigned int fkey(float f) {
    unsigned int u = __float_as_uint(f);
    return (u & 0x80000000u) ? ~u : (u | 0x80000000u);
}

__device__ __forceinline__ unsigned int tf32_bits(float x) {
    unsigned int u;
    asm("cvt.rna.tf32.f32 %0, %1;" : "=r"(u) : "f"(x));
    return u;
}

// ---------------- MLP GEMM: O = act(A @ W + b), N = DH = 256 ---------------
__global__ __launch_bounds__(NTHREADS, 2)
void mlp_gemm_kernel(const float* __restrict__ in0, const float* __restrict__ in1,
                     const float* __restrict__ Wd0, const float* __restrict__ Wd1,
                     const float* __restrict__ bd0, const float* __restrict__ bd1,
                     int layer)
{
    const int z = blockIdx.z;
    const float* A;
    float* O;
    int K, relu;
    if (layer == 0) {
        A = z ? in1 : in0;
        O = z ? g_hid1 : g_hid0;
        K = DIN; relu = 1;
    } else {
        A = z ? g_hid1 : g_hid0;
        O = z ? g_b2 : g_a2;
        K = DH; relu = 0;
    }
    const float* W = z ? Wd1 : Wd0;
    const float* bias = z ? bd1 : bd0;

    __shared__ float As[BK][BM];
    __shared__ float Bs[BK][BN];

    const int tid = threadIdx.x;
    const int tx = tid & 15, ty = tid >> 4;
    const int r0 = blockIdx.y * BM;
    const int c0 = blockIdx.x * BN;

    float acc[8][8];
#pragma unroll
    for (int i = 0; i < 8; i++)
#pragma unroll
        for (int j = 0; j < 8; j++) acc[i][j] = 0.0f;

    for (int k0 = 0; k0 < K; k0 += BK) {
#pragma unroll
        for (int i = 0; i < 2; i++) {
            int f = tid * 2 + i;
            int row = f >> 2;
            int kq = (f & 3) << 2;
            float4 v = *(const float4*)(A + (size_t)(r0 + row) * K + k0 + kq);
            As[kq + 0][row] = v.x; As[kq + 1][row] = v.y;
            As[kq + 2][row] = v.z; As[kq + 3][row] = v.w;
        }
#pragma unroll
        for (int i = 0; i < 2; i++) {
            int f = tid * 2 + i;
            int kk = f >> 5;
            int nq = (f & 31) << 2;
            *(float4*)&Bs[kk][nq] =
                *(const float4*)(W + (size_t)(k0 + kk) * DH + c0 + nq);
        }
        __syncthreads();
#pragma unroll
        for (int kk = 0; kk < BK; kk++) {
            float a[8], b[8];
            *(float4*)&a[0] = *(float4*)&As[kk][ty * 8];
            *(float4*)&a[4] = *(float4*)&As[kk][ty * 8 + 4];
            *(float4*)&b[0] = *(float4*)&Bs[kk][tx * 8];
            *(float4*)&b[4] = *(float4*)&Bs[kk][tx * 8 + 4];
#pragma unroll
            for (int i = 0; i < 8; i++)
#pragma unroll
                for (int j = 0; j < 8; j++)
                    acc[i][j] = fmaf(a[i], b[j], acc[i][j]);
        }
        __syncthreads();
    }

    float bv[8];
    *(float4*)&bv[0] = *(const float4*)(bias + c0 + tx * 8);
    *(float4*)&bv[4] = *(const float4*)(bias + c0 + tx * 8 + 4);

#pragma unroll
    for (int i = 0; i < 8; i++) {
        int row = r0 + ty * 8 + i;
        float f[8];
#pragma unroll
        for (int j = 0; j < 8; j++) f[j] = acc[i][j] + bv[j];
        if (relu) {
#pragma unroll
            for (int j = 0; j < 8; j++) f[j] = fmaxf(f[j], 0.0f);
            *(float4*)(O + (size_t)row * DH + c0 + tx * 8) = *(float4*)&f[0];
            *(float4*)(O + (size_t)row * DH + c0 + tx * 8 + 4) = *(float4*)&f[4];
        } else {
            float hi[8], lo[8];
#pragma unroll
            for (int j = 0; j < 8; j++) {
                hi[j] = __uint_as_float(tf32_bits(f[j]));
                lo[j] = f[j] - hi[j];           // EXACT residual: hi+lo == f bitwise
            }
            float* dst = O + (size_t)row * KTOT + c0 + tx * 8;
            *(float4*)(dst)           = *(float4*)&hi[0];
            *(float4*)(dst + 4)       = *(float4*)&hi[4];
            *(float4*)(dst + 256)     = *(float4*)&lo[0];
            *(float4*)(dst + 256 + 4) = *(float4*)&lo[4];
        }
    }
}

// ---------------- sim GEMM: mma.sync tf32, 3-term hi/lo split ---------------
__device__ __forceinline__ void cp16(uint32_t smem_dst, const float* src) {
    asm volatile("cp.async.cg.shared.global [%0], [%1], 16;"
                 :: "r"(smem_dst), "l"(src) : "memory");
}

__global__ __launch_bounds__(256, 2)
void sim_mma_kernel(float* __restrict__ C)
{
    __shared__ float As[2][128 * SROWSTRIDE];
    __shared__ float Bs[2][128 * SROWSTRIDE];
    __shared__ float wmax[8];

    const int tid = threadIdx.x;
    const int lid = tid & 31, wid = tid >> 5;
    const int warp_m = wid >> 2, warp_n = wid & 3;   // 2 x 4 warps
    const int gr = lid >> 2, gc = lid & 3;
    const int m0 = blockIdx.y * 128;
    const int n0 = blockIdx.x * 128;

    const float* __restrict__ Ag = g_a2 + (size_t)m0 * KTOT;
    const float* __restrict__ Bg = g_b2 + (size_t)n0 * KTOT;

    const int ld_row = tid >> 1;
    const int ld_h = (tid & 1) * 8;
    const uint32_t sa_base = (uint32_t)__cvta_generic_to_shared(
        &As[0][ld_row * SROWSTRIDE + ld_h]);
    const uint32_t sb_base = (uint32_t)__cvta_generic_to_shared(
        &Bs[0][ld_row * SROWSTRIDE + ld_h]);
    const uint32_t buf_bytes = 128 * SROWSTRIDE * 4;

    float acc[4][4][4];
#pragma unroll
    for (int i = 0; i < 4; i++)
#pragma unroll
        for (int j = 0; j < 4; j++)
#pragma unroll
            for (int q = 0; q < 4; q++) acc[i][j][q] = 0.0f;

    // stage s: term t = s/16; A offset: (t==2?lo:hi), B offset: (t==1?lo:hi)
#define ISSUE(s)                                                               \
    do {                                                                       \
        int t_ = (s) >> 4;                                                     \
        int r_ = ((s) & 15) * SBK;                                             \
        int ao_ = (t_ == 2 ? 256 : 0) + r_;                                    \
        int bo_ = (t_ == 1 ? 256 : 0) + r_;                                    \
        const float* a_ = Ag + (size_t)ld_row * KTOT + ao_ + ld_h;             \
        const float* b_ = Bg + (size_t)ld_row * KTOT + bo_ + ld_h;             \
        uint32_t da_ = sa_base + ((s) & 1) * buf_bytes;                        \
        uint32_t db_ = sb_base + ((s) & 1) * buf_bytes;                        \
        cp16(da_, a_); cp16(da_ + 16, a_ + 4);                                 \
        cp16(db_, b_); cp16(db_ + 16, b_ + 4);                                 \
        asm volatile("cp.async.commit_group;" ::: "memory");                   \
    } while (0)

    ISSUE(0);
    ISSUE(1);

#pragma unroll 1
    for (int s = 0; s < NSTAGE; s++) {
        if (s < NSTAGE - 1)
            asm volatile("cp.async.wait_group 1;" ::: "memory");
        else
            asm volatile("cp.async.wait_group 0;" ::: "memory");
        __syncthreads();

        const float* Asb = As[s & 1];
        const float* Bsb = Bs[s & 1];
#pragma unroll
        for (int kk = 0; kk < SBK; kk += 8) {
            uint32_t a[4][4], b[4][2];
#pragma unroll
            for (int i = 0; i < 4; i++) {
                const float* p = Asb + (warp_m * 64 + i * 16 + gr) * SROWSTRIDE + kk + gc;
                a[i][0] = __float_as_uint(p[0]);
                a[i][1] = __float_as_uint(p[8 * SROWSTRIDE]);
                a[i][2] = __float_as_uint(p[4]);
                a[i][3] = __float_as_uint(p[8 * SROWSTRIDE + 4]);
            }
#pragma unroll
            for (int j = 0; j < 4; j++) {
                const float* p = Bsb + (warp_n * 32 + j * 8 + gr) * SROWSTRIDE + kk + gc;
                b[j][0] = __float_as_uint(p[0]);
                b[j][1] = __float_as_uint(p[4]);
            }
#pragma unroll
            for (int i = 0; i < 4; i++)
#pragma unroll
                for (int j = 0; j < 4; j++) {
                    asm volatile(
                        "mma.sync.aligned.m16n8k8.row.col.f32.tf32.tf32.f32 "
                        "{%0,%1,%2,%3}, {%4,%5,%6,%7}, {%8,%9}, {%0,%1,%2,%3};"
                        : "+f"(acc[i][j][0]), "+f"(acc[i][j][1]),
                          "+f"(acc[i][j][2]), "+f"(acc[i][j][3])
                        : "r"(a[i][0]), "r"(a[i][1]), "r"(a[i][2]), "r"(a[i][3]),
                          "r"(b[j][0]), "r"(b[j][1]));
                }
        }
        __syncthreads();
        if (s + 2 < NSTAGE) ISSUE(s + 2);
    }
#undef ISSUE

    // ---- epilogue: direct streaming stores + block max ----
    float bmax = -3.0e38f;
#pragma unroll
    for (int i = 0; i < 4; i++) {
#pragma unroll
        for (int j = 0; j < 4; j++) {
            int row = m0 + warp_m * 64 + i * 16 + gr;
            int col = n0 + warp_n * 32 + j * 8 + gc * 2;
            float* d0 = C + (size_t)row * NCOLS + col;
            float* d1 = d0 + 8 * (size_t)NCOLS;
            asm volatile("st.global.cs.v2.f32 [%0], {%1,%2};"
                         :: "l"(d0), "f"(acc[i][j][0]), "f"(acc[i][j][1]) : "memory");
            asm volatile("st.global.cs.v2.f32 [%0], {%1,%2};"
                         :: "l"(d1), "f"(acc[i][j][2]), "f"(acc[i][j][3]) : "memory");
            bmax = fmaxf(bmax, fmaxf(fmaxf(acc[i][j][0], acc[i][j][1]),
                                     fmaxf(acc[i][j][2], acc[i][j][3])));
        }
    }
#pragma unroll
    for (int o = 16; o; o >>= 1) bmax = fmaxf(bmax, __shfl_xor_sync(~0u, bmax, o));
    if (lid == 0) wmax[wid] = bmax;
    __syncthreads();
    if (tid == 0) {
        float mm = wmax[0];
#pragma unroll
        for (int i = 1; i < 8; i++) mm = fmaxf(mm, wmax[i]);
        g_blockmax[blockIdx.y * gridDim.x + blockIdx.x] = mm;
    }
}

// ---------------- threshold: radix-select over 4096 block maxima -----------
__global__ void thresh_kernel()
{
    __shared__ unsigned int cs[32];
    __shared__ unsigned int Ts;
    const int tid = threadIdx.x;  // 1024 threads
    const int w = tid >> 5, l = tid & 31;
    unsigned int k[4];
#pragma unroll
    for (int q = 0; q < 4; q++) k[q] = fkey(g_blockmax[tid + q * 1024]);
    if (tid == 0) Ts = 0u;
    __syncthreads();
    for (int bit = 31; bit >= 8; bit--) {
        unsigned int Tc = Ts | (1u << bit);
        unsigned int c = 0;
#pragma unroll
        for (int q = 0; q < 4; q++) c += (unsigned)(k[q] >= Tc);
#pragma unroll
        for (int o = 16; o; o >>= 1) c += __shfl_xor_sync(~0u, c, o);
        if (l == 0) cs[w] = c;
        __syncthreads();
        if (tid == 0) {
            unsigned int tot = 0;
            for (int i = 0; i < 32; i++) tot += cs[i];
            if (tot >= TOPK) Ts = Tc;
        }
        __syncthreads();
    }
    if (tid == 0) {
        unsigned int T = Ts;
        float f;
        if (T < 0x01000000u) f = -3.0e38f;
        else if (T & 0x80000000u) f = __uint_as_float(T ^ 0x80000000u);
        else f = __uint_as_float(~T);
        // relaxed margin: tf32-GEMM ordering error insurance (~1e-4 relative)
        g_thresh = f - (fabsf(f) * 1e-4f + 1e-6f);
        g_ccount = 0;
    }
}

// ---------------- collect candidates >= threshold ---------------------------
__device__ __forceinline__ void push_cand(float v, unsigned int idx)
{
    unsigned int pos = atomicAdd(&g_ccount, 1u);
    if (pos < CAND_BUF) {
        unsigned long long e =
            ((unsigned long long)fkey(v) << 32) | (unsigned int)(~idx);
        g_cand[pos] = e;
    }
}

__global__ void collect_kernel(const float* __restrict__ S)
{
    const float T = g_thresh;
    const size_t total4 = (size_t)MROWS * NCOLS / 4;
    const size_t stride = (size_t)gridDim.x * blockDim.x;
    for (size_t q = (size_t)blockIdx.x * blockDim.x + threadIdx.x;
         q < total4; q += stride) {
        float4 v = ((const float4*)S)[q];
        unsigned int base = (unsigned int)(q * 4);
        if (v.x >= T) push_cand(v.x, base + 0);
        if (v.y >= T) push_cand(v.y, base + 1);
        if (v.z >= T) push_cand(v.z, base + 2);
        if (v.w >= T) push_cand(v.w, base + 3);
    }
}

// ---------------- recompute candidate values exactly (fp64, warp/cand) -----
__global__ void recompute_kernel()
{
    unsigned int cnt = g_ccount;
    if (cnt > CAND_BUF) cnt = CAND_BUF;
    const int gw = (blockIdx.x * blockDim.x + threadIdx.x) >> 5;
    const int nw = (gridDim.x * blockDim.x) >> 5;
    const int lid = threadIdx.x & 31;
    for (unsigned int i = gw; i < cnt; i += nw) {
        unsigned long long e = g_cand[i];
        unsigned int idx = ~(unsigned int)(e & 0xFFFFFFFFull);
        int r = idx >> 13, c = idx & (NCOLS - 1);
        const float* ar = g_a2 + (size_t)r * KTOT;
        const float* br = g_b2 + (size_t)c * KTOT;
        double s = 0.0;
#pragma unroll
        for (int k = 0; k < 8; k++) {
            int kk = lid + k * 32;
            double av = (double)(ar[kk] + ar[kk + 256]);   // exact fp32 md0 value
            double bv = (double)(br[kk] + br[kk + 256]);
            s = fma(av, bv, s);
        }
#pragma unroll
        for (int o = 16; o; o >>= 1) s += __shfl_down_sync(0xffffffffu, s, o);
        if (lid == 0) {
            float v = (float)s;
            g_cand[i] = ((unsigned long long)fkey(v) << 32)
                      | (unsigned long long)(e & 0xFFFFFFFFull);
        }
    }
}

// ---------------- final: sort candidates, emit (row, col) pairs ------------
__global__ void final_kernel(float* __restrict__ out)
{
    __shared__ unsigned long long s[CAND_SORT];
    __shared__ unsigned long long red[32];
    const int tid = threadIdx.x;  // 1024 threads
    unsigned int cnt = g_ccount;
    if (cnt > CAND_BUF) cnt = CAND_BUF;

    if (cnt <= CAND_SORT) {
        for (int i = tid; i < CAND_SORT; i += 1024)
            s[i] = (i < (int)cnt) ? g_cand[i] : 0ull;
        __syncthreads();
        for (int k = 2; k <= CAND_SORT; k <<= 1) {
            for (int j = k >> 1; j > 0; j >>= 1) {
                for (int i = tid; i < CAND_SORT; i += 1024) {
                    int ixj = i ^ j;
                    if (ixj > i) {
                        bool desc = ((i & k) == 0);
                        unsigned long long a = s[i], b = s[ixj];
                        if (desc ? (a < b) : (a > b)) { s[i] = b; s[ixj] = a; }
                    }
                }
                __syncthreads();
            }
        }
        for (int i = tid; i < TOPK; i += 1024) {
            unsigned int idx = ~(unsigned int)(s[i] & 0xFFFFFFFFull);
            out[2 * i + 0] = (float)(idx >> 13);
            out[2 * i + 1] = (float)(idx & (NCOLS - 1));
        }
    } else {
        for (int r = 0; r < TOPK; r++) {
            unsigned long long best = 0ull;
            for (unsigned int i = tid; i < cnt; i += 1024) {
                unsigned long long v = g_cand[i];
                if (v > best) best = v;
            }
#pragma unroll
            for (int o = 16; o; o >>= 1) {
                unsigned long long other = __shfl_down_sync(0xffffffffu, best, o);
                if (other > best) best = other;
            }
            if ((tid & 31) == 0) red[tid >> 5] = best;
            __syncthreads();
            if (tid < 32) {
                unsigned long long b = red[tid];
#pragma unroll
                for (int o = 16; o; o >>= 1) {
                    unsigned long long other = __shfl_down_sync(0xffffffffu, b, o);
                    if (other > b) b = other;
                }
                if (tid == 0) red[0] = b;
            }
            __syncthreads();
            best = red[0];
            for (unsigned int i = tid; i < cnt; i += 1024)
                if (g_cand[i] == best) g_cand[i] = 0ull;
            if (tid == 0) {
                unsigned int idx = ~(unsigned int)(best & 0xFFFFFFFFull);
                out[2 * r + 0] = (float)(idx >> 13);
                out[2 * r + 1] = (float)(idx & (NCOLS - 1));
            }
            __syncthreads();
        }
    }
}

// ---------------- launch ----------------------------------------------------
extern "C" void kernel_launch(void* const* d_in, const int* in_sizes, int n_in,
                              void* d_out, int out_size)
{
    const float* desc0 = (const float*)d_in[0];
    const float* desc1 = (const float*)d_in[1];
    const float* W0a = (const float*)d_in[2];
    const float* b0a = (const float*)d_in[3];
    const float* W0b = (const float*)d_in[4];
    const float* b0b = (const float*)d_in[5];
    const float* W1a = (const float*)d_in[6];
    const float* b1a = (const float*)d_in[7];
    const float* W1b = (const float*)d_in[8];
    const float* b1b = (const float*)d_in[9];

    float* out = (float*)d_out;
    float* sim = out + 2 * TOPK;  // indices first, then sim [8192, 8192]

    dim3 mgrid(DH / BN, MROWS / BM, 2);   // (2, 64, 2)
    mlp_gemm_kernel<<<mgrid, NTHREADS>>>(desc0, desc1, W0a, W1a, b0a, b1a, 0);
    mlp_gemm_kernel<<<mgrid, NTHREADS>>>(desc0, desc1, W0b, W1b, b0b, b1b, 1);

    dim3 sgrid(NBX, NBY);                 // (64, 64)
    sim_mma_kernel<<<sgrid, 256>>>(sim);

    thresh_kernel<<<1, 1024>>>();
    collect_kernel<<<2048, 256>>>(sim);
    recompute_kernel<<<256, 256>>>();
    final_kernel<<<1, 1024>>>(out);
}